// round 13
// baseline (speedup 1.0000x reference)
#include <cuda_runtime.h>
#include <cuda_bf16.h>

// Problem constants
#define NUM_CW   512
#define CDIM     64
#define HWSZ     4096
#define T_TOK    131072
#define GAMMA_F  0.99f
#define BM       128              // tokens per CTA
#define BNC      32               // codewords per chunk
#define N_CHUNK  (NUM_CW / BNC)   // 16
#define EPS_GAP  4e-3f            // ambiguity threshold (worst-case err ~2e-3)
#define XS_PAD   66               // xs row stride (floats)

// Output layout: q | codebook_new | N_new | m_new
#define OFF_CB  8388608
#define OFF_N   8421376
#define OFF_M   8421888

// Scratch (device globals; zeroed at load, re-zeroed by finalize each call)
__device__ float g_counts[NUM_CW];
__device__ float g_sums[NUM_CW * CDIM];
__device__ float g_cnorm[NUM_CW];
__device__ unsigned int g_cbH[NUM_CW * CDIM / 2];  // [k][c-pair] bf16 hi
__device__ unsigned int g_cbL[NUM_CW * CDIM / 2];  // [k][c-pair] bf16 lo

__device__ __forceinline__ unsigned int pack_bf2(float v0, float v1) {
    __nv_bfloat162 h = __floats2bfloat162_rn(v0, v1);
    return *(unsigned int*)&h;
}
__device__ __forceinline__ void split_pair(float v0, float v1,
                                           unsigned int& hi, unsigned int& lo) {
    __nv_bfloat16 h0 = __float2bfloat16(v0), h1 = __float2bfloat16(v1);
    float r0 = v0 - __bfloat162float(h0), r1 = v1 - __bfloat162float(h1);
    __nv_bfloat16 l0 = __float2bfloat16(r0), l1 = __float2bfloat16(r1);
    hi = ((unsigned int)__bfloat16_as_ushort(h1) << 16) |
         (unsigned int)__bfloat16_as_ushort(h0);
    lo = ((unsigned int)__bfloat16_as_ushort(l1) << 16) |
         (unsigned int)__bfloat16_as_ushort(l0);
}

#define MMA_BF16(acc, a, b)                                                  \
    asm volatile(                                                            \
        "mma.sync.aligned.m16n8k16.row.col.f32.bf16.bf16.f32 "               \
        "{%0,%1,%2,%3}, {%4,%5,%6,%7}, {%8,%9}, {%0,%1,%2,%3};"              \
        : "+f"((acc)[0]), "+f"((acc)[1]), "+f"((acc)[2]), "+f"((acc)[3])     \
        : "r"((a)[0]), "r"((a)[1]), "r"((a)[2]), "r"((a)[3]),                \
          "r"((b)[0]), "r"((b)[1]))

// ---------- init: norms + bf16 hi/lo split of the codebook ----------
__global__ void init_kernel(const float* __restrict__ cb) {
    int i = blockIdx.x * blockDim.x + threadIdx.x;   // 0..32767
    float v = cb[i];
    float s = v * v;
#pragma unroll
    for (int off = 16; off > 0; off >>= 1)
        s += __shfl_down_sync(0xFFFFFFFFu, s, off);
    if ((threadIdx.x & 31) == 0)
        atomicAdd(&g_cnorm[i >> 6], s);
    if (i < NUM_CW * CDIM / 2) {
        unsigned int hi, lo;
        split_pair(cb[2 * i], cb[2 * i + 1], hi, lo);
        g_cbH[i] = hi;
        g_cbL[i] = lo;
    }
}

// ---------- main: HMMA split-bf16 distance GEMM + exactness repair ----------
__global__ __launch_bounds__(128)
void assign_mma_kernel(const float* __restrict__ x,
                       const float* __restrict__ codebook,
                       float* __restrict__ out) {
    __shared__ __align__(16) float xs[BM][XS_PAD];          // 33 KB fp32 x
    __shared__ __align__(16) unsigned int bsH[BNC][33];     // 4.1 KB
    __shared__ __align__(16) unsigned int bsL[BNC][33];     // 4.1 KB
    __shared__ float snorm[NUM_CW];                         // 2 KB
    __shared__ int   bidx[BM];
    __shared__ int   list[BM];
    __shared__ int   nflag;
    __shared__ unsigned long long red;

    const int tid = threadIdx.x;
    const int w   = tid >> 5;         // warp 0..3 (owns tokens w*32..+31)
    const int lane = tid & 31;
    const int g   = lane >> 2;        // group 0..7
    const int t   = lane & 3;         // thread-in-group
    const int t0  = blockIdx.x * BM;
    const int n   = t0 >> 12;
    const long base = (long)n * (CDIM * HWSZ) + (t0 & (HWSZ - 1));

    if (tid == 0) nflag = 0;
#pragma unroll
    for (int i = tid; i < NUM_CW; i += 128) snorm[i] = g_cnorm[i];

    // Load x tile transposed into xs[tok][c] (coalesced gmem reads).
    {
        const float* xsrc = x + base;
#pragma unroll
        for (int i = 0; i < 16; i++) {
            int idx = tid + i * 128;      // 0..2047 float4 slots
            int c = idx >> 5, q4 = idx & 31;
            float4 v = *(const float4*)(xsrc + c * HWSZ + q4 * 4);
            xs[q4 * 4 + 0][c] = v.x;
            xs[q4 * 4 + 1][c] = v.y;
            xs[q4 * 4 + 2][c] = v.z;
            xs[q4 * 4 + 3][c] = v.w;
        }
    }
    __syncthreads();

    // Build resident A fragments (hi/lo) for this warp's 32 tokens.
    unsigned int ahi[2][4][4], alo[2][4][4];
#pragma unroll
    for (int mt = 0; mt < 2; mt++) {
#pragma unroll
        for (int kt = 0; kt < 4; kt++) {
            int r0 = w * 32 + mt * 16 + g;
            int r1 = r0 + 8;
            int k0 = kt * 16 + 2 * t;
            int k1 = k0 + 8;
            float2 p;
            p = *(const float2*)&xs[r0][k0];
            split_pair(p.x, p.y, ahi[mt][kt][0], alo[mt][kt][0]);
            p = *(const float2*)&xs[r1][k0];
            split_pair(p.x, p.y, ahi[mt][kt][1], alo[mt][kt][1]);
            p = *(const float2*)&xs[r0][k1];
            split_pair(p.x, p.y, ahi[mt][kt][2], alo[mt][kt][2]);
            p = *(const float2*)&xs[r1][k1];
            split_pair(p.x, p.y, ahi[mt][kt][3], alo[mt][kt][3]);
        }
    }

    // Per-thread top-2 state: [mt][rowhalf]
    float b1s[2][2] = {{3.4e38f, 3.4e38f}, {3.4e38f, 3.4e38f}};
    float b2s[2][2] = {{3.4e38f, 3.4e38f}, {3.4e38f, 3.4e38f}};
    int   i1s[2][2] = {{0, 0}, {0, 0}};

    for (int ch = 0; ch < N_CHUNK; ch++) {
        __syncthreads();
        // Stage B chunk (32 cw x 32 c-pairs) hi/lo into padded smem.
#pragma unroll
        for (int i = 0; i < 8; i++) {
            int idx = tid + i * 128;      // 0..1023
            int cw = idx >> 5, cp = idx & 31;
            bsH[cw][cp] = g_cbH[(ch * BNC + cw) * 32 + cp];
            bsL[cw][cp] = g_cbL[(ch * BNC + cw) * 32 + cp];
        }
        __syncthreads();

#pragma unroll
        for (int nt = 0; nt < 4; nt++) {
            const int bn = nt * 8 + g;
            unsigned int bh[4][2], bl[4][2];
#pragma unroll
            for (int kt = 0; kt < 4; kt++) {
                bh[kt][0] = bsH[bn][kt * 8 + t];
                bh[kt][1] = bsH[bn][kt * 8 + t + 4];
                bl[kt][0] = bsL[bn][kt * 8 + t];
                bl[kt][1] = bsL[bn][kt * 8 + t + 4];
            }
#pragma unroll
            for (int mt = 0; mt < 2; mt++) {
                float acc[4] = {0.0f, 0.0f, 0.0f, 0.0f};
#pragma unroll
                for (int kt = 0; kt < 4; kt++) MMA_BF16(acc, ahi[mt][kt], bh[kt]);
#pragma unroll
                for (int kt = 0; kt < 4; kt++) MMA_BF16(acc, alo[mt][kt], bh[kt]);
#pragma unroll
                for (int kt = 0; kt < 4; kt++) MMA_BF16(acc, ahi[mt][kt], bl[kt]);

                int col0 = ch * BNC + nt * 8 + 2 * t;
                float nr0 = snorm[col0], nr1 = snorm[col0 + 1];
                float d00 = fmaf(-2.0f, acc[0], nr0);
                float d01 = fmaf(-2.0f, acc[1], nr1);
                float d10 = fmaf(-2.0f, acc[2], nr0);
                float d11 = fmaf(-2.0f, acc[3], nr1);
                // rowhalf 0 (row g)
                if (d00 < b1s[mt][0]) { b2s[mt][0] = b1s[mt][0]; b1s[mt][0] = d00; i1s[mt][0] = col0; }
                else if (d00 < b2s[mt][0]) b2s[mt][0] = d00;
                if (d01 < b1s[mt][0]) { b2s[mt][0] = b1s[mt][0]; b1s[mt][0] = d01; i1s[mt][0] = col0 + 1; }
                else if (d01 < b2s[mt][0]) b2s[mt][0] = d01;
                // rowhalf 1 (row g+8)
                if (d10 < b1s[mt][1]) { b2s[mt][1] = b1s[mt][1]; b1s[mt][1] = d10; i1s[mt][1] = col0; }
                else if (d10 < b2s[mt][1]) b2s[mt][1] = d10;
                if (d11 < b1s[mt][1]) { b2s[mt][1] = b1s[mt][1]; b1s[mt][1] = d11; i1s[mt][1] = col0 + 1; }
                else if (d11 < b2s[mt][1]) b2s[mt][1] = d11;
            }
        }
    }

    // Merge top-2 across the 4 lanes of each group (they share token rows).
#pragma unroll
    for (int mt = 0; mt < 2; mt++) {
#pragma unroll
        for (int rh = 0; rh < 2; rh++) {
            float b1 = b1s[mt][rh], b2 = b2s[mt][rh];
            int   i1 = i1s[mt][rh];
#pragma unroll
            for (int off = 1; off < 4; off <<= 1) {
                float ob1 = __shfl_xor_sync(0xFFFFFFFFu, b1, off);
                float ob2 = __shfl_xor_sync(0xFFFFFFFFu, b2, off);
                int   oi1 = __shfl_xor_sync(0xFFFFFFFFu, i1, off);
                if (ob1 < b1 || (ob1 == b1 && oi1 < i1)) {
                    b2 = fminf(ob2, b1);
                    b1 = ob1; i1 = oi1;
                } else {
                    b2 = fminf(b2, ob1);
                }
            }
            if (t == 0) {
                int tok = w * 32 + mt * 16 + rh * 8 + g;
                bidx[tok] = i1;
                if (b2 - b1 < EPS_GAP) {
                    int pos = atomicAdd(&nflag, 1);
                    list[pos] = tok;
                }
            }
        }
    }
    __syncthreads();

    // Exact fp32 re-argmin for ambiguous tokens (bit-identical to reference).
    const int nf = nflag;
    for (int f = 0; f < nf; f++) {
        int tokf = list[f];
        if (tid == 0) red = 0xFFFFFFFFFFFFFFFFull;
        __syncthreads();
        unsigned long long mine = 0xFFFFFFFFFFFFFFFFull;
#pragma unroll
        for (int jj = 0; jj < 4; jj++) {
            int k = tid * 4 + jj;
            const float* cw = codebook + k * CDIM;
            float dot = 0.0f;
#pragma unroll
            for (int c = 0; c < CDIM; c++) dot = fmaf(xs[tokf][c], cw[c], dot);
            float d = fmaf(-2.0f, dot, snorm[k]);
            unsigned int u = __float_as_uint(d);
            u = (u & 0x80000000u) ? ~u : (u | 0x80000000u);
            unsigned long long p = ((unsigned long long)u << 32) | (unsigned int)k;
            if (p < mine) mine = p;
        }
        atomicMin(&red, mine);
        __syncthreads();
        if (tid == 0) bidx[tokf] = (int)(red & 0xFFFFFFFFu);
        __syncthreads();
    }
    __syncthreads();

    // Final write: q + EMA stats (thread = token). x read back from smem.
    {
        const int bk = bidx[tid];
        atomicAdd(&g_counts[bk], 1.0f);
        const float4* cw4 = (const float4*)(codebook + bk * CDIM);
        float* qo = out + base + tid;
        float* sums = &g_sums[bk * CDIM];
#pragma unroll
        for (int i = 0; i < CDIM / 4; i++) {
            float4 v = cw4[i];
            qo[(4 * i + 0) * HWSZ] = v.x;
            qo[(4 * i + 1) * HWSZ] = v.y;
            qo[(4 * i + 2) * HWSZ] = v.z;
            qo[(4 * i + 3) * HWSZ] = v.w;
        }
#pragma unroll
        for (int c = 0; c < CDIM; c++)
            atomicAdd(&sums[c], xs[tid][c]);
    }
}

// One thread per (k, c). Also resets scratch for the next call.
__global__ void finalize_kernel(const float* __restrict__ N_state,
                                const float* __restrict__ m_state,
                                float* __restrict__ out) {
    int i = blockIdx.x * blockDim.x + threadIdx.x;
    if (i >= NUM_CW * CDIM) return;
    int k = i / CDIM;
    float cnt = g_counts[k];
    bool occ = cnt > 0.0f;
    float Nold = N_state[k];
    float Nn = occ ? (Nold * GAMMA_F + cnt * (1.0f - GAMMA_F)) : Nold;
    float mold = m_state[i];
    float mn = occ ? (mold * GAMMA_F + g_sums[i] * (1.0f - GAMMA_F)) : mold;
    out[OFF_M + i]  = mn;
    out[OFF_CB + i] = mn / Nn;
    g_sums[i] = 0.0f;
    if ((i % CDIM) == 0) out[OFF_N + k] = Nn;
    if (i < NUM_CW) { g_counts[i] = 0.0f; g_cnorm[i] = 0.0f; }
}

extern "C" void kernel_launch(void* const* d_in, const int* in_sizes, int n_in,
                              void* d_out, int out_size) {
    const float* x        = (const float*)d_in[0];
    const float* codebook = (const float*)d_in[1];
    const float* N_state  = (const float*)d_in[2];
    const float* m_state  = (const float*)d_in[3];
    float* out = (float*)d_out;

    init_kernel<<<NUM_CW * CDIM / 256, 256>>>(codebook);
    assign_mma_kernel<<<T_TOK / BM, 128>>>(x, codebook, out);
    finalize_kernel<<<(NUM_CW * CDIM + 255) / 256, 256>>>(N_state, m_state, out);
}

// round 14
// speedup vs baseline: 1.0770x; 1.0770x over previous
#include <cuda_runtime.h>
#include <cuda_bf16.h>

// Problem constants
#define NUM_CW   512
#define CDIM     64
#define HWSZ     4096
#define T_TOK    131072
#define GAMMA_F  0.99f
#define BM       128              // tokens per CTA
#define BNC      32               // codewords per chunk
#define N_CHUNK  (NUM_CW / BNC)   // 16
#define EPS_GAP  4e-3f            // ambiguity threshold (worst-case err ~2e-3)
#define XS_PAD   66               // xs row stride (floats)

// Output layout: q | codebook_new | N_new | m_new
#define OFF_CB  8388608
#define OFF_N   8421376
#define OFF_M   8421888

// Scratch (device globals; zeroed at load, re-zeroed by finalize each call)
__device__ float g_counts[NUM_CW];
__device__ float g_sums[NUM_CW * CDIM];
__device__ float g_cnorm[NUM_CW];
__device__ unsigned int g_cbH[NUM_CW * CDIM / 2];  // [k][c-pair] bf16 hi
__device__ unsigned int g_cbL[NUM_CW * CDIM / 2];  // [k][c-pair] bf16 lo

__device__ __forceinline__ void split_pair(float v0, float v1,
                                           unsigned int& hi, unsigned int& lo) {
    __nv_bfloat16 h0 = __float2bfloat16(v0), h1 = __float2bfloat16(v1);
    float r0 = v0 - __bfloat162float(h0), r1 = v1 - __bfloat162float(h1);
    __nv_bfloat16 l0 = __float2bfloat16(r0), l1 = __float2bfloat16(r1);
    hi = ((unsigned int)__bfloat16_as_ushort(h1) << 16) |
         (unsigned int)__bfloat16_as_ushort(h0);
    lo = ((unsigned int)__bfloat16_as_ushort(l1) << 16) |
         (unsigned int)__bfloat16_as_ushort(l0);
}

#define MMA_BF16(acc, a, b)                                                  \
    asm volatile(                                                            \
        "mma.sync.aligned.m16n8k16.row.col.f32.bf16.bf16.f32 "               \
        "{%0,%1,%2,%3}, {%4,%5,%6,%7}, {%8,%9}, {%0,%1,%2,%3};"              \
        : "+f"((acc)[0]), "+f"((acc)[1]), "+f"((acc)[2]), "+f"((acc)[3])     \
        : "r"((a)[0]), "r"((a)[1]), "r"((a)[2]), "r"((a)[3]),                \
          "r"((b)[0]), "r"((b)[1]))

// ---------- init: norms + bf16 hi/lo split of the codebook ----------
__global__ void init_kernel(const float* __restrict__ cb) {
    int i = blockIdx.x * blockDim.x + threadIdx.x;   // 0..32767
    float v = cb[i];
    float s = v * v;
#pragma unroll
    for (int off = 16; off > 0; off >>= 1)
        s += __shfl_down_sync(0xFFFFFFFFu, s, off);
    if ((threadIdx.x & 31) == 0)
        atomicAdd(&g_cnorm[i >> 6], s);
    if (i < NUM_CW * CDIM / 2) {
        unsigned int hi, lo;
        split_pair(cb[2 * i], cb[2 * i + 1], hi, lo);
        g_cbH[i] = hi;
        g_cbL[i] = lo;
    }
}

// ---------- main: HMMA split-bf16 distance GEMM + exactness repair ----------
__global__ __launch_bounds__(128, 3)
void assign_mma_kernel(const float* __restrict__ x,
                       const float* __restrict__ codebook,
                       float* __restrict__ out) {
    __shared__ __align__(16) float xs[BM][XS_PAD];          // 33 KB fp32 x
    __shared__ __align__(16) unsigned int bsH[BNC][33];     // 4.1 KB
    __shared__ __align__(16) unsigned int bsL[BNC][33];     // 4.1 KB
    __shared__ float snorm[NUM_CW];                         // 2 KB
    __shared__ int   bidx[BM];
    __shared__ int   list[BM];
    __shared__ int   nflag;
    __shared__ unsigned long long red;

    const int tid = threadIdx.x;
    const int w   = tid >> 5;         // warp 0..3 (owns tokens w*32..+31)
    const int lane = tid & 31;
    const int g   = lane >> 2;        // group 0..7
    const int t   = lane & 3;         // thread-in-group
    const int t0  = blockIdx.x * BM;
    const int n   = t0 >> 12;
    const long base = (long)n * (CDIM * HWSZ) + (t0 & (HWSZ - 1));

    if (tid == 0) nflag = 0;
#pragma unroll
    for (int i = tid; i < NUM_CW; i += 128) snorm[i] = g_cnorm[i];

    // Load x tile transposed into xs[tok][c] (coalesced gmem reads).
    {
        const float* xsrc = x + base;
#pragma unroll
        for (int i = 0; i < 16; i++) {
            int idx = tid + i * 128;      // 0..2047 float4 slots
            int c = idx >> 5, q4 = idx & 31;
            float4 v = *(const float4*)(xsrc + c * HWSZ + q4 * 4);
            xs[q4 * 4 + 0][c] = v.x;
            xs[q4 * 4 + 1][c] = v.y;
            xs[q4 * 4 + 2][c] = v.z;
            xs[q4 * 4 + 3][c] = v.w;
        }
    }
    __syncthreads();

    // Build resident A fragments (hi/lo) for this warp's 32 tokens.
    unsigned int ahi[2][4][4], alo[2][4][4];
#pragma unroll
    for (int mt = 0; mt < 2; mt++) {
#pragma unroll
        for (int kt = 0; kt < 4; kt++) {
            int r0 = w * 32 + mt * 16 + g;
            int r1 = r0 + 8;
            int k0 = kt * 16 + 2 * t;
            int k1 = k0 + 8;
            float2 p;
            p = *(const float2*)&xs[r0][k0];
            split_pair(p.x, p.y, ahi[mt][kt][0], alo[mt][kt][0]);
            p = *(const float2*)&xs[r1][k0];
            split_pair(p.x, p.y, ahi[mt][kt][1], alo[mt][kt][1]);
            p = *(const float2*)&xs[r0][k1];
            split_pair(p.x, p.y, ahi[mt][kt][2], alo[mt][kt][2]);
            p = *(const float2*)&xs[r1][k1];
            split_pair(p.x, p.y, ahi[mt][kt][3], alo[mt][kt][3]);
        }
    }

    // Per-thread top-2 state: [mt][rowhalf]
    float b1s[2][2] = {{3.4e38f, 3.4e38f}, {3.4e38f, 3.4e38f}};
    float b2s[2][2] = {{3.4e38f, 3.4e38f}, {3.4e38f, 3.4e38f}};
    int   i1s[2][2] = {{0, 0}, {0, 0}};

    for (int ch = 0; ch < N_CHUNK; ch++) {
        __syncthreads();
        // Stage B chunk (32 cw x 32 c-pairs) hi/lo into padded smem.
#pragma unroll
        for (int i = 0; i < 8; i++) {
            int idx = tid + i * 128;      // 0..1023
            int cw = idx >> 5, cp = idx & 31;
            bsH[cw][cp] = g_cbH[(ch * BNC + cw) * 32 + cp];
            bsL[cw][cp] = g_cbL[(ch * BNC + cw) * 32 + cp];
        }
        __syncthreads();

#pragma unroll
        for (int nt = 0; nt < 4; nt++) {
            const int bn = nt * 8 + g;
            unsigned int bh[4][2], bl[4][2];
#pragma unroll
            for (int kt = 0; kt < 4; kt++) {
                bh[kt][0] = bsH[bn][kt * 8 + t];
                bh[kt][1] = bsH[bn][kt * 8 + t + 4];
                bl[kt][0] = bsL[bn][kt * 8 + t];
                bl[kt][1] = bsL[bn][kt * 8 + t + 4];
            }
#pragma unroll
            for (int mt = 0; mt < 2; mt++) {
                // Three independent accumulation chains (hi*hi, lo*hi, hi*lo)
                float a1[4] = {0.f, 0.f, 0.f, 0.f};
                float a2[4] = {0.f, 0.f, 0.f, 0.f};
                float a3[4] = {0.f, 0.f, 0.f, 0.f};
#pragma unroll
                for (int kt = 0; kt < 4; kt++) {
                    MMA_BF16(a1, ahi[mt][kt], bh[kt]);
                    MMA_BF16(a2, alo[mt][kt], bh[kt]);
                    MMA_BF16(a3, ahi[mt][kt], bl[kt]);
                }
                float acc0 = a1[0] + a2[0] + a3[0];
                float acc1 = a1[1] + a2[1] + a3[1];
                float acc2 = a1[2] + a2[2] + a3[2];
                float acc3 = a1[3] + a2[3] + a3[3];

                int col0 = ch * BNC + nt * 8 + 2 * t;
                float nr0 = snorm[col0], nr1 = snorm[col0 + 1];
                float d00 = fmaf(-2.0f, acc0, nr0);
                float d01 = fmaf(-2.0f, acc1, nr1);
                float d10 = fmaf(-2.0f, acc2, nr0);
                float d11 = fmaf(-2.0f, acc3, nr1);
                // rowhalf 0 (row g)
                if (d00 < b1s[mt][0]) { b2s[mt][0] = b1s[mt][0]; b1s[mt][0] = d00; i1s[mt][0] = col0; }
                else if (d00 < b2s[mt][0]) b2s[mt][0] = d00;
                if (d01 < b1s[mt][0]) { b2s[mt][0] = b1s[mt][0]; b1s[mt][0] = d01; i1s[mt][0] = col0 + 1; }
                else if (d01 < b2s[mt][0]) b2s[mt][0] = d01;
                // rowhalf 1 (row g+8)
                if (d10 < b1s[mt][1]) { b2s[mt][1] = b1s[mt][1]; b1s[mt][1] = d10; i1s[mt][1] = col0; }
                else if (d10 < b2s[mt][1]) b2s[mt][1] = d10;
                if (d11 < b1s[mt][1]) { b2s[mt][1] = b1s[mt][1]; b1s[mt][1] = d11; i1s[mt][1] = col0 + 1; }
                else if (d11 < b2s[mt][1]) b2s[mt][1] = d11;
            }
        }
    }

    // Merge top-2 across the 4 lanes of each group (they share token rows).
#pragma unroll
    for (int mt = 0; mt < 2; mt++) {
#pragma unroll
        for (int rh = 0; rh < 2; rh++) {
            float b1 = b1s[mt][rh], b2 = b2s[mt][rh];
            int   i1 = i1s[mt][rh];
#pragma unroll
            for (int off = 1; off < 4; off <<= 1) {
                float ob1 = __shfl_xor_sync(0xFFFFFFFFu, b1, off);
                float ob2 = __shfl_xor_sync(0xFFFFFFFFu, b2, off);
                int   oi1 = __shfl_xor_sync(0xFFFFFFFFu, i1, off);
                if (ob1 < b1 || (ob1 == b1 && oi1 < i1)) {
                    b2 = fminf(ob2, b1);
                    b1 = ob1; i1 = oi1;
                } else {
                    b2 = fminf(b2, ob1);
                }
            }
            if (t == 0) {
                int tok = w * 32 + mt * 16 + rh * 8 + g;
                bidx[tok] = i1;
                if (b2 - b1 < EPS_GAP) {
                    int pos = atomicAdd(&nflag, 1);
                    list[pos] = tok;
                }
            }
        }
    }
    __syncthreads();

    // Exact fp32 re-argmin for ambiguous tokens (bit-identical to reference).
    const int nf = nflag;
    for (int f = 0; f < nf; f++) {
        int tokf = list[f];
        if (tid == 0) red = 0xFFFFFFFFFFFFFFFFull;
        __syncthreads();
        unsigned long long mine = 0xFFFFFFFFFFFFFFFFull;
#pragma unroll
        for (int jj = 0; jj < 4; jj++) {
            int k = tid * 4 + jj;
            const float* cw = codebook + k * CDIM;
            float dot = 0.0f;
#pragma unroll
            for (int c = 0; c < CDIM; c++) dot = fmaf(xs[tokf][c], cw[c], dot);
            float d = fmaf(-2.0f, dot, snorm[k]);
            unsigned int u = __float_as_uint(d);
            u = (u & 0x80000000u) ? ~u : (u | 0x80000000u);
            unsigned long long p = ((unsigned long long)u << 32) | (unsigned int)k;
            if (p < mine) mine = p;
        }
        atomicMin(&red, mine);
        __syncthreads();
        if (tid == 0) bidx[tokf] = (int)(red & 0xFFFFFFFFu);
        __syncthreads();
    }
    __syncthreads();

    // Final write: q + EMA stats (thread = token). x read back from smem.
    {
        const int bk = bidx[tid];
        atomicAdd(&g_counts[bk], 1.0f);
        const float4* cw4 = (const float4*)(codebook + bk * CDIM);
        float* qo = out + base + tid;
        float* sums = &g_sums[bk * CDIM];
#pragma unroll
        for (int i = 0; i < CDIM / 4; i++) {
            float4 v = cw4[i];
            qo[(4 * i + 0) * HWSZ] = v.x;
            qo[(4 * i + 1) * HWSZ] = v.y;
            qo[(4 * i + 2) * HWSZ] = v.z;
            qo[(4 * i + 3) * HWSZ] = v.w;
        }
#pragma unroll
        for (int c = 0; c < CDIM; c++)
            atomicAdd(&sums[c], xs[tid][c]);
    }
}

// One thread per (k, c). Also resets scratch for the next call.
__global__ void finalize_kernel(const float* __restrict__ N_state,
                                const float* __restrict__ m_state,
                                float* __restrict__ out) {
    int i = blockIdx.x * blockDim.x + threadIdx.x;
    if (i >= NUM_CW * CDIM) return;
    int k = i / CDIM;
    float cnt = g_counts[k];
    bool occ = cnt > 0.0f;
    float Nold = N_state[k];
    float Nn = occ ? (Nold * GAMMA_F + cnt * (1.0f - GAMMA_F)) : Nold;
    float mold = m_state[i];
    float mn = occ ? (mold * GAMMA_F + g_sums[i] * (1.0f - GAMMA_F)) : mold;
    out[OFF_M + i]  = mn;
    out[OFF_CB + i] = mn / Nn;
    g_sums[i] = 0.0f;
    if ((i % CDIM) == 0) out[OFF_N + k] = Nn;
    if (i < NUM_CW) { g_counts[i] = 0.0f; g_cnorm[i] = 0.0f; }
}

extern "C" void kernel_launch(void* const* d_in, const int* in_sizes, int n_in,
                              void* d_out, int out_size) {
    const float* x        = (const float*)d_in[0];
    const float* codebook = (const float*)d_in[1];
    const float* N_state  = (const float*)d_in[2];
    const float* m_state  = (const float*)d_in[3];
    float* out = (float*)d_out;

    init_kernel<<<NUM_CW * CDIM / 256, 256>>>(codebook);
    assign_mma_kernel<<<T_TOK / BM, 128>>>(x, codebook, out);
    finalize_kernel<<<(NUM_CW * CDIM + 255) / 256, 256>>>(N_state, m_state, out);
}